// round 2
// baseline (speedup 1.0000x reference)
#include <cuda_runtime.h>
#include <math.h>
#include <stdint.h>

// Problem constants
#define MDIM 384
#define LDIM 25
#define LPAD 32
#define NIMG 64
#define HIMG 28
#define FHW  5
#define OHDIM 24
#define PDIM 576
#define JITTER_F 1e-6f
#define SKS 68              // sKT row stride (floats), 68*4=272 bytes (16B aligned)

// ---------------- device scratch ----------------
__device__ float g_Zs[MDIM*LPAD];        // Z / lengthscale, padded stride 32
__device__ float g_Zsq[MDIM];
__device__ float g_Xs[NIMG*HIMG*HIMG];
__device__ float g_Kuu[MDIM*MDIM];
__device__ float g_W[MDIM*MDIM];         // X1 then scratch
__device__ float g_W2[MDIM*MDIM];        // final W = Kuu^-1
__device__ float g_R[MDIM*MDIM];
__device__ float g_Ls[MDIM*MDIM];
__device__ float g_qS[MDIM*MDIM];
__device__ float g_T[MDIM*MDIM];
__device__ unsigned long long g_Cdup[MDIM*MDIM];  // C stored duplicated (v,v) per entry
__device__ float g_alpha[MDIM];

__device__ __forceinline__ unsigned long long ffma2(unsigned long long a,
                                                    unsigned long long b,
                                                    unsigned long long c) {
    unsigned long long d;
    asm("fma.rn.f32x2 %0, %1, %2, %3;" : "=l"(d) : "l"(a), "l"(b), "l"(c));
    return d;
}
__device__ __forceinline__ void unpack2(unsigned long long v, float& lo, float& hi) {
    asm("mov.b64 {%0, %1}, %2;" : "=f"(lo), "=f"(hi) : "l"(v));
}

// ---------------- prep ----------------
__global__ void prep_kernel(const float* __restrict__ X, const float* __restrict__ Z,
                            const float* __restrict__ qsqrt,
                            const float* __restrict__ plen) {
    float inv_l = 1.0f / plen[0];
    int stride = gridDim.x * blockDim.x;
    int tid = blockIdx.x * blockDim.x + threadIdx.x;
    for (int i = tid; i < NIMG*HIMG*HIMG; i += stride) g_Xs[i] = X[i] * inv_l;
    for (int i = tid; i < MDIM*LPAD; i += stride) {
        int m = i / LPAD, l = i - m*LPAD;
        g_Zs[i] = (l < LDIM) ? Z[m*LDIM + l] * inv_l : 0.0f;
    }
    for (int i = tid; i < MDIM*MDIM; i += stride) {
        int r = i / MDIM, c = i - r*MDIM;
        g_Ls[i] = (c <= r) ? qsqrt[i] : 0.0f;
    }
}

__global__ void zsq_kernel() {
    int m = blockIdx.x * blockDim.x + threadIdx.x;
    if (m < MDIM) {
        float s = 0.0f;
        #pragma unroll
        for (int l = 0; l < LDIM; l++) { float z = g_Zs[m*LPAD + l]; s += z*z; }
        g_Zsq[m] = s;
    }
}

// ---------------- Kuu and Newton-Schulz X1 (elementwise) ----------------
__global__ void kuu_kernel(const float* __restrict__ pvar) {
    int idx = blockIdx.x * blockDim.x + threadIdx.x;
    if (idx >= MDIM*MDIM) return;
    int i = idx / MDIM, j = idx - i*MDIM;
    float dot = 0.0f;
    #pragma unroll
    for (int l = 0; l < LDIM; l++) dot += g_Zs[i*LPAD + l] * g_Zs[j*LPAD + l];
    float d2 = fmaxf(g_Zsq[i] + g_Zsq[j] - 2.0f*dot, 0.0f);
    float v = pvar[0] * __expf(-0.5f * d2);
    if (i == j) v += JITTER_F;
    g_Kuu[idx] = v;
    // X1 = w0*(2I - w0*Kuu)
    float w0 = 1.0f / (pvar[0] + JITTER_F);
    g_W[idx] = w0 * ((i == j ? 2.0f : 0.0f) - w0 * v);
}

// ---------------- 384x384 GEMM ----------------
// mode 0: C=A*B ; mode 1: C=2I-A*B ; mode 3: dup-store of (A*B - D)
__global__ __launch_bounds__(256) void gemm384(const float* __restrict__ A,
                                               const float* __restrict__ B,
                                               float* __restrict__ C,
                                               const float* __restrict__ D,
                                               int mode, int transB) {
    __shared__ float As[32][33];
    __shared__ float Bs[32][33];
    int tid = threadIdx.x;
    int brow = blockIdx.y * 32;
    int bcol = blockIdx.x * 32;
    int lr = tid >> 5;
    int lc = tid & 31;
    int ty = tid >> 4;
    int tx = tid & 15;
    float acc00 = 0.f, acc01 = 0.f, acc10 = 0.f, acc11 = 0.f;

    for (int kt = 0; kt < MDIM; kt += 32) {
        #pragma unroll
        for (int l = 0; l < 4; l++) {
            int r = lr + l*8;
            As[r][lc] = A[(brow + r)*MDIM + kt + lc];
            if (!transB) Bs[r][lc] = B[(kt + r)*MDIM + bcol + lc];
            else         Bs[lc][r] = B[(bcol + r)*MDIM + kt + lc];
        }
        __syncthreads();
        #pragma unroll
        for (int k = 0; k < 32; k++) {
            float a0 = As[2*ty][k],   a1 = As[2*ty+1][k];
            float b0 = Bs[k][2*tx],   b1 = Bs[k][2*tx+1];
            acc00 += a0*b0; acc01 += a0*b1;
            acc10 += a1*b0; acc11 += a1*b1;
        }
        __syncthreads();
    }
    int r0 = brow + 2*ty, c0 = bcol + 2*tx;
    float o[2][2] = {{acc00, acc01}, {acc10, acc11}};
    #pragma unroll
    for (int r = 0; r < 2; r++) {
        #pragma unroll
        for (int c = 0; c < 2; c++) {
            int gi = (r0 + r)*MDIM + (c0 + c);
            float v = o[r][c];
            if (mode == 1) {
                v = ((r0 + r) == (c0 + c) ? 2.0f : 0.0f) - v;
                C[gi] = v;
            } else if (mode == 3) {
                v = v - D[gi];
                reinterpret_cast<float2*>(C)[gi] = make_float2(v, v);
            } else {
                C[gi] = v;
            }
        }
    }
}

// ---------------- alpha = W * q_mu ----------------
__global__ void alpha_kernel(const float* __restrict__ Wf, const float* __restrict__ qmu) {
    int i = blockIdx.x * blockDim.x + threadIdx.x;
    if (i < MDIM) {
        float s = 0.0f;
        for (int j = 0; j < MDIM; j++) s += Wf[i*MDIM + j] * qmu[j];
        g_alpha[i] = s;
    }
}

// ---------------- fused: Kuf gen + mean + quadratic form ----------------
// one block per patch position p (all 64 images), 256 threads
// smem: sKT[384][68] + sZ[384][32] + sP[64][32] + salpha[384] + spsq[64] + smean[256] + svar[64]
#define SM_SKT   0
#define SM_SZ    (MDIM*SKS)                       // 26112
#define SM_SP    (SM_SZ + MDIM*LPAD)              // +12288
#define SM_ALPHA (SM_SP + NIMG*LPAD)              // +2048
#define SM_PSQ   (SM_ALPHA + MDIM)                // +384
#define SM_MEAN  (SM_PSQ + NIMG)                  // +64
#define SM_VAR   (SM_MEAN + 4*NIMG)               // +256
#define SM_TOTAL (SM_VAR + NIMG)                  // +64  -> 41216 floats = 164864 B

__global__ __launch_bounds__(256, 1) void fused_kernel(const float* __restrict__ pvar,
                                                       float* __restrict__ out_mean,
                                                       float* __restrict__ out_var) {
    extern __shared__ float sm[];
    float* sKT    = sm + SM_SKT;
    float* sZ     = sm + SM_SZ;
    float* sP     = sm + SM_SP;
    float* salpha = sm + SM_ALPHA;
    float* spsq   = sm + SM_PSQ;
    float* smean  = sm + SM_MEAN;
    float* svar   = sm + SM_VAR;

    int p = blockIdx.x;
    int oh = p / OHDIM, ow = p - oh*OHDIM;
    int tid = threadIdx.x;
    float v = pvar[0];

    // phase 0: cooperative loads
    {
        const float4* zsrc = reinterpret_cast<const float4*>(g_Zs);
        float4* zdst = reinterpret_cast<float4*>(sZ);
        for (int i = tid; i < MDIM*LPAD/4; i += 256) zdst[i] = zsrc[i];
    }
    for (int i = tid; i < NIMG*LPAD; i += 256) {
        int n = i >> 5, l = i & 31;
        float val = 0.0f;
        if (l < LDIM) {
            int fh = l / FHW, fw = l - fh*FHW;
            val = g_Xs[n*(HIMG*HIMG) + (oh + fh)*HIMG + (ow + fw)];
        }
        sP[i] = val;
    }
    for (int i = tid; i < MDIM; i += 256) salpha[i] = g_alpha[i];
    __syncthreads();

    // phase 1: patch squared norms
    if (tid < NIMG) {
        float s = 0.0f;
        #pragma unroll
        for (int l = 0; l < LDIM; l++) { float x = sP[tid*LPAD + l]; s += x*x; }
        spsq[tid] = s;
    }
    __syncthreads();

    // phase 2: K generation -> sKT[m][n]
    {
        int n = tid & 63;
        int mgrp = tid >> 6;   // 0..3
        float4 rp[8];
        const float4* pp = reinterpret_cast<const float4*>(&sP[n*LPAD]);
        #pragma unroll
        for (int i = 0; i < 8; i++) rp[i] = pp[i];
        float psq = spsq[n];
        #pragma unroll 2
        for (int mi = 0; mi < 96; mi++) {
            int m = mgrp*96 + mi;
            const float4* zz = reinterpret_cast<const float4*>(&sZ[m*LPAD]);
            float dot = 0.0f;
            #pragma unroll
            for (int i = 0; i < 8; i++) {
                float4 z = zz[i];
                dot += z.x*rp[i].x + z.y*rp[i].y + z.z*rp[i].z + z.w*rp[i].w;
            }
            float d2 = fmaxf(g_Zsq[m] + psq - 2.0f*dot, 0.0f);
            sKT[m*SKS + n] = v * __expf(-0.5f*d2);
        }
    }
    __syncthreads();

    // phase 3: mean partials (no sync needed before phase 4: both read sKT)
    {
        int n = tid & 63;
        int seg = tid >> 6;
        float s = 0.0f;
        #pragma unroll 4
        for (int mi = 0; mi < 96; mi++) {
            int m = seg*96 + mi;
            s += sKT[m*SKS + n] * salpha[m];
        }
        smean[seg*64 + n] = s;
    }

    // phase 4: quadratic form  var_n = sum_{m,m'} K[m][n] C[m][m'] K[m'][n]
    {
        int tx = tid & 15;        // column group
        int ty = tid >> 4;        // 0..15, rows r0..r0+3
        int r0 = ty * 4;
        uint32_t skt_u32 = (uint32_t)__cvta_generic_to_shared(sKT);
        float vacc[4] = {0.f, 0.f, 0.f, 0.f};

        for (int jc = 0; jc < 6; jc++) {
            int c0 = jc*64 + tx*4;
            unsigned long long accP[2][4];
            #pragma unroll
            for (int i = 0; i < 2; i++)
                #pragma unroll
                for (int j = 0; j < 4; j++) accP[i][j] = 0ull;

            uint32_t kaddr = skt_u32 + (uint32_t)(r0 * 4);
            const unsigned long long* crow = &g_Cdup[c0];
            #pragma unroll 4
            for (int kk = 0; kk < MDIM; kk++) {
                unsigned long long k01, k23;
                asm("ld.shared.v2.b64 {%0, %1}, [%2];"
                    : "=l"(k01), "=l"(k23) : "r"(kaddr));
                ulonglong2 cA = *reinterpret_cast<const ulonglong2*>(crow);
                ulonglong2 cB = *reinterpret_cast<const ulonglong2*>(crow + 2);
                accP[0][0] = ffma2(k01, cA.x, accP[0][0]);
                accP[1][0] = ffma2(k23, cA.x, accP[1][0]);
                accP[0][1] = ffma2(k01, cA.y, accP[0][1]);
                accP[1][1] = ffma2(k23, cA.y, accP[1][1]);
                accP[0][2] = ffma2(k01, cB.x, accP[0][2]);
                accP[1][2] = ffma2(k23, cB.x, accP[1][2]);
                accP[0][3] = ffma2(k01, cB.y, accP[0][3]);
                accP[1][3] = ffma2(k23, cB.y, accP[1][3]);
                kaddr += SKS * 4;
                crow += MDIM;
            }
            // epilogue: multiply by K[c0+c][row] and accumulate
            #pragma unroll
            for (int c = 0; c < 4; c++) {
                float a0, a1, a2, a3;
                unpack2(accP[0][c], a0, a1);
                unpack2(accP[1][c], a2, a3);
                const float* kcol = &sKT[(c0 + c)*SKS + r0];
                vacc[0] += a0 * kcol[0];
                vacc[1] += a1 * kcol[1];
                vacc[2] += a2 * kcol[2];
                vacc[3] += a3 * kcol[3];
            }
        }
        // reduce over the 16 tx lanes (width-16 segments within warp)
        #pragma unroll
        for (int r = 0; r < 4; r++) {
            float s = vacc[r];
            s += __shfl_down_sync(0xffffffffu, s, 8, 16);
            s += __shfl_down_sync(0xffffffffu, s, 4, 16);
            s += __shfl_down_sync(0xffffffffu, s, 2, 16);
            s += __shfl_down_sync(0xffffffffu, s, 1, 16);
            if (tx == 0) svar[r0 + r] = s;
        }
    }
    __syncthreads();

    // phase 5: write outputs
    if (tid < NIMG) {
        float mn = smean[tid] + smean[64 + tid] + smean[128 + tid] + smean[192 + tid];
        out_mean[(size_t)tid * PDIM + p] = mn;
        out_var[(size_t)tid * PDIM + p]  = v + svar[tid];
    }
}

// ---------------- host launch ----------------
extern "C" void kernel_launch(void* const* d_in, const int* in_sizes, int n_in,
                              void* d_out, int out_size) {
    const float* X    = (const float*)d_in[0];
    const float* Z    = (const float*)d_in[1];
    const float* qmu  = (const float*)d_in[2];
    const float* qsq  = (const float*)d_in[3];
    const float* pvar = (const float*)d_in[4];
    const float* plen = (const float*)d_in[5];
    float* out = (float*)d_out;
    float* out_mean = out;
    float* out_var  = out + (size_t)NIMG*PDIM;

    float *pKuu, *pW, *pW2, *pR, *pLs, *pqS, *pT;
    unsigned long long* pCdup;
    cudaGetSymbolAddress((void**)&pKuu,  g_Kuu);
    cudaGetSymbolAddress((void**)&pW,    g_W);
    cudaGetSymbolAddress((void**)&pW2,   g_W2);
    cudaGetSymbolAddress((void**)&pR,    g_R);
    cudaGetSymbolAddress((void**)&pLs,   g_Ls);
    cudaGetSymbolAddress((void**)&pqS,   g_qS);
    cudaGetSymbolAddress((void**)&pT,    g_T);
    cudaGetSymbolAddress((void**)&pCdup, g_Cdup);

    prep_kernel<<<64, 256>>>(X, Z, qsq, plen);
    zsq_kernel<<<2, 256>>>();
    kuu_kernel<<<(MDIM*MDIM + 255)/256, 256>>>(pvar);   // also writes X1 into g_W

    dim3 ggrid(12, 12);
    // Newton-Schulz iteration 2 (iteration 1 was elementwise): W2 = X1(2I - Kuu X1)
    gemm384<<<ggrid, 256>>>(pKuu, pW,  pR,  nullptr, 1, 0);
    gemm384<<<ggrid, 256>>>(pW,   pR,  pW2, nullptr, 0, 0);
    // qS = Ls Ls^T ; T = W qS ; Cdup = dup(T W - W)
    gemm384<<<ggrid, 256>>>(pLs, pLs, pqS, nullptr, 0, 1);
    gemm384<<<ggrid, 256>>>(pW2, pqS, pT,  nullptr, 0, 0);
    gemm384<<<ggrid, 256>>>(pT,  pW2, (float*)pCdup, pW2, 3, 0);

    alpha_kernel<<<3, 128>>>(pW2, qmu);

    int smem_bytes = SM_TOTAL * (int)sizeof(float);
    cudaFuncSetAttribute(fused_kernel, cudaFuncAttributeMaxDynamicSharedMemorySize, smem_bytes);
    fused_kernel<<<PDIM, 256, smem_bytes>>>(pvar, out_mean, out_var);
}

// round 3
// speedup vs baseline: 1.8774x; 1.8774x over previous
#include <cuda_runtime.h>
#include <math.h>
#include <stdint.h>

#define MDIM 384
#define LDIM 25
#define LPAD 32
#define NIMG 64
#define HIMG 28
#define FHW  5
#define OHDIM 24
#define PDIM 576
#define JITTER_F 1e-6f

// ---------------- device scratch ----------------
__device__ float g_Zs[MDIM*LPAD];
__device__ float g_Zsq[MDIM];
__device__ float g_Xs[NIMG*HIMG*HIMG];
__device__ float g_Kuu[MDIM*MDIM];
__device__ float g_X1[MDIM*MDIM];
__device__ float g_W2[MDIM*MDIM];
__device__ float g_R[MDIM*MDIM];
__device__ float g_Ls[MDIM*MDIM];
__device__ float g_E[MDIM*MDIM];
__device__ float g_T[MDIM*MDIM];
__device__ float g_Cm[MDIM*MDIM];
__device__ float g_alpha[MDIM];

// ---------------- helpers ----------------
__device__ __forceinline__ unsigned long long ffma2(unsigned long long a,
                                                    unsigned long long b,
                                                    unsigned long long c) {
    unsigned long long d;
    asm("fma.rn.f32x2 %0, %1, %2, %3;" : "=l"(d) : "l"(a), "l"(b), "l"(c));
    return d;
}
__device__ __forceinline__ unsigned long long pack2(float lo, float hi) {
    unsigned long long v;
    asm("mov.b64 %0, {%1, %2};" : "=l"(v) : "f"(lo), "f"(hi));
    return v;
}
__device__ __forceinline__ void unpack2(unsigned long long v, float& lo, float& hi) {
    asm("mov.b64 {%0, %1}, %2;" : "=f"(lo), "=f"(hi) : "l"(v));
}
__device__ __forceinline__ void cpasync16(uint32_t saddr, const void* gptr) {
    asm volatile("cp.async.ca.shared.global [%0], [%1], 16;" :: "r"(saddr), "l"(gptr));
}
__device__ __forceinline__ void cpcommit() {
    asm volatile("cp.async.commit_group;");
}
template<int N> __device__ __forceinline__ void cpwait() {
    asm volatile("cp.async.wait_group %0;" :: "n"(N));
}

// ---------------- prep ----------------
__global__ void prep_kernel(const float* __restrict__ X, const float* __restrict__ Z,
                            const float* __restrict__ qsqrt,
                            const float* __restrict__ plen) {
    float inv_l = 1.0f / plen[0];
    int stride = gridDim.x * blockDim.x;
    int tid = blockIdx.x * blockDim.x + threadIdx.x;
    for (int i = tid; i < NIMG*HIMG*HIMG; i += stride) g_Xs[i] = X[i] * inv_l;
    for (int i = tid; i < MDIM*LPAD; i += stride) {
        int m = i / LPAD, l = i - m*LPAD;
        g_Zs[i] = (l < LDIM) ? Z[m*LDIM + l] * inv_l : 0.0f;
    }
    for (int i = tid; i < MDIM*MDIM; i += stride) {
        int r = i / MDIM, c = i - r*MDIM;
        g_Ls[i] = (c <= r) ? qsqrt[i] : 0.0f;
    }
}

__global__ void zsq_kernel() {
    int m = blockIdx.x * blockDim.x + threadIdx.x;
    if (m < MDIM) {
        float s = 0.0f;
        #pragma unroll
        for (int l = 0; l < LDIM; l++) { float z = g_Zs[m*LPAD + l]; s += z*z; }
        g_Zsq[m] = s;
    }
}

// ---------------- Kuu + Newton X1 (elementwise) ----------------
__global__ void kuu_kernel(const float* __restrict__ pvar) {
    int idx = blockIdx.x * blockDim.x + threadIdx.x;
    if (idx >= MDIM*MDIM) return;
    int i = idx / MDIM, j = idx - i*MDIM;
    float dot = 0.0f;
    #pragma unroll
    for (int l = 0; l < LDIM; l++) dot += g_Zs[i*LPAD + l] * g_Zs[j*LPAD + l];
    float d2 = fmaxf(g_Zsq[i] + g_Zsq[j] - 2.0f*dot, 0.0f);
    float v = pvar[0] * __expf(-0.5f * d2);
    if (i == j) v += JITTER_F;
    g_Kuu[idx] = v;
    float w0 = 1.0f / (pvar[0] + JITTER_F);
    g_X1[idx] = w0 * ((i == j ? 2.0f : 0.0f) - w0 * v);
}

// ---------------- 384^3 GEMM, cp.async double-buffered, dual-op via blockIdx.z ----
// mode 0: C = A*B ; mode 1: C = 2I - A*B ; mode 2: C = A*B - D
__global__ __launch_bounds__(256) void gemm_db(
    const float* A0, const float* B0, float* C0, const float* D0, int mode0, int tb0,
    const float* A1, const float* B1, float* C1, const float* D1, int mode1, int tb1)
{
    const float* A = A0; const float* B = B0; float* C = C0; const float* D = D0;
    int mode = mode0, transB = tb0;
    if (blockIdx.z == 1) { A = A1; B = B1; C = C1; D = D1; mode = mode1; transB = tb1; }

    __shared__ float As[2][32][36];
    __shared__ float Bs[2][32][36];
    int tid = threadIdx.x;
    int brow = blockIdx.y * 32;
    int bcol = blockIdx.x * 32;
    int row = tid >> 3;          // 0..31
    int c4  = (tid & 7) * 4;     // 0..28
    int ty = tid >> 4;           // 0..15
    int tx = tid & 15;           // 0..15

    uint32_t aBase = (uint32_t)__cvta_generic_to_shared(&As[0][0][0]);
    uint32_t bBase = (uint32_t)__cvta_generic_to_shared(&Bs[0][0][0]);
    const int BUF = 32*36*4;

    auto issue = [&](int s, int kt) {
        cpasync16(aBase + s*BUF + (row*36 + c4)*4, A + (brow + row)*MDIM + kt + c4);
        const float* bsrc = transB ? (B + (bcol + row)*MDIM + kt + c4)
                                   : (B + (kt + row)*MDIM + bcol + c4);
        cpasync16(bBase + s*BUF + (row*36 + c4)*4, bsrc);
    };

    issue(0, 0);  cpcommit();
    issue(1, 32); cpcommit();

    float acc00 = 0.f, acc01 = 0.f, acc10 = 0.f, acc11 = 0.f;

    for (int t = 0; t < 12; t++) {
        cpwait<1>();
        __syncthreads();
        int s = t & 1;
        if (!transB) {
            #pragma unroll
            for (int k = 0; k < 32; k++) {
                float a0 = As[s][2*ty][k], a1 = As[s][2*ty+1][k];
                float b0 = Bs[s][k][2*tx], b1 = Bs[s][k][2*tx+1];
                acc00 += a0*b0; acc01 += a0*b1;
                acc10 += a1*b0; acc11 += a1*b1;
            }
        } else {
            #pragma unroll
            for (int k = 0; k < 32; k++) {
                float a0 = As[s][2*ty][k], a1 = As[s][2*ty+1][k];
                float b0 = Bs[s][2*tx][k], b1 = Bs[s][2*tx+1][k];
                acc00 += a0*b0; acc01 += a0*b1;
                acc10 += a1*b0; acc11 += a1*b1;
            }
        }
        __syncthreads();
        if (t + 2 < 12) issue(s, (t + 2) * 32);
        cpcommit();  // possibly-empty group keeps pipeline count uniform
    }

    int r0 = brow + 2*ty, c0 = bcol + 2*tx;
    float o[2][2] = {{acc00, acc01}, {acc10, acc11}};
    #pragma unroll
    for (int r = 0; r < 2; r++)
        #pragma unroll
        for (int c = 0; c < 2; c++) {
            int gi = (r0 + r)*MDIM + (c0 + c);
            float v = o[r][c];
            if (mode == 1)      v = ((r0 + r) == (c0 + c) ? 2.0f : 0.0f) - v;
            else if (mode == 2) v = v - D[gi];
            C[gi] = v;
        }
}

// ---------------- alpha = W2 * q_mu ----------------
__global__ void alpha_kernel(const float* __restrict__ qmu) {
    int i = blockIdx.x * blockDim.x + threadIdx.x;
    if (i < MDIM) {
        float s = 0.0f;
        for (int j = 0; j < MDIM; j++) s += g_W2[i*MDIM + j] * qmu[j];
        g_alpha[i] = s;
    }
}

// ---------------- mega: K gen + mean + quadratic form ----------------
// smem layout (bytes):
//   [0, 98304)        sK[384][64]
//   [98304, 196608)   region2: phase1 = sZ/sP/alpha/psq/mean ; phase2 = sC double buffer 2x49152
//   [196608, 196864)  svar[64]
#define SMEM_MEGA_B 196864
#define CTILE_B 49152

__global__ __launch_bounds__(256, 1) void mega_kernel(const float* __restrict__ pvar,
                                                      float* __restrict__ out_mean,
                                                      float* __restrict__ out_var) {
    extern __shared__ float sm[];
    float* sK     = sm;                  // [384][64]
    float* r2     = sm + 98304/4;
    float* sZ     = r2;                  // [384][32]
    float* sP     = r2 + 12288;          // [64][32]
    float* salpha = r2 + 14336;          // 384
    float* spsq   = r2 + 14720;          // 64
    float* smean  = r2 + 14784;          // 256
    float* svar   = sm + 196608/4;       // 64

    int p = blockIdx.x;
    int oh = p / OHDIM, ow = p - oh*OHDIM;
    int tid = threadIdx.x;
    float v = pvar[0];

    // ---- phase 0: cooperative loads ----
    {
        const float4* zsrc = reinterpret_cast<const float4*>(g_Zs);
        float4* zdst = reinterpret_cast<float4*>(sZ);
        for (int i = tid; i < MDIM*LPAD/4; i += 256) zdst[i] = zsrc[i];
    }
    for (int i = tid; i < NIMG*LPAD; i += 256) {
        int n = i >> 5, l = i & 31;
        float val = 0.0f;
        if (l < LDIM) {
            int fh = l / FHW, fw = l - fh*FHW;
            val = g_Xs[n*(HIMG*HIMG) + (oh + fh)*HIMG + (ow + fw)];
        }
        sP[i] = val;
    }
    for (int i = tid; i < MDIM; i += 256) salpha[i] = g_alpha[i];
    __syncthreads();

    if (tid < NIMG) {
        float s = 0.0f;
        #pragma unroll
        for (int l = 0; l < LDIM; l++) { float x = sP[tid*LPAD + l]; s += x*x; }
        spsq[tid] = s;
    }
    __syncthreads();

    // ---- phase 1: K generation (-> sK[m][n]) + mean partials ----
    {
        int n = tid & 63;
        int mgrp = tid >> 6;
        float4 rp[8];
        const float4* pp = reinterpret_cast<const float4*>(&sP[n*LPAD]);
        #pragma unroll
        for (int i = 0; i < 8; i++) rp[i] = pp[i];
        float psq = spsq[n];
        float mpart = 0.0f;
        #pragma unroll 2
        for (int mi = 0; mi < 96; mi++) {
            int m = mgrp*96 + mi;
            const float4* zz = reinterpret_cast<const float4*>(&sZ[m*LPAD]);
            float dot = 0.0f;
            #pragma unroll
            for (int i = 0; i < 8; i++) {
                float4 z = zz[i];
                dot += z.x*rp[i].x + z.y*rp[i].y + z.z*rp[i].z + z.w*rp[i].w;
            }
            float d2 = fmaxf(g_Zsq[m] + psq - 2.0f*dot, 0.0f);
            float k = v * __expf(-0.5f*d2);
            sK[m*64 + n] = k;
            mpart += k * salpha[m];
        }
        smean[mgrp*64 + n] = mpart;
    }
    __syncthreads();
    if (tid < NIMG)
        out_mean[(size_t)tid * PDIM + p] =
            smean[tid] + smean[64 + tid] + smean[128 + tid] + smean[192 + tid];
    __syncthreads();  // release region2 for C tiles

    // ---- phase 2: quadratic form, C streamed via cp.async double buffer ----
    uint32_t sK_u32 = (uint32_t)__cvta_generic_to_shared(sK);
    uint32_t sC_u32 = (uint32_t)__cvta_generic_to_shared(r2);

    auto issueC = [&](int t) {
        const float* src = g_Cm + t*32*MDIM;
        uint32_t dst = sC_u32 + (t & 1)*CTILE_B;
        #pragma unroll
        for (int i = 0; i < 12; i++) {
            int f4 = tid + i*256;               // 0..3071
            cpasync16(dst + f4*16, src + f4*4);
        }
    };

    issueC(0); cpcommit();
    issueC(1); cpcommit();

    int tx = tid & 15;          // m' group
    int ty = tid >> 4;          // np group
    int r0 = ty * 4;

    unsigned long long accP[48];
    #pragma unroll
    for (int i = 0; i < 48; i++) accP[i] = 0ull;

    for (int t = 0; t < 12; t++) {
        cpwait<1>();
        __syncthreads();
        uint32_t kaddr = sK_u32 + (uint32_t)((t*32*64 + r0) * 4);
        uint32_t cbase = sC_u32 + (t & 1)*CTILE_B + tx*32;
        #pragma unroll 2
        for (int kk = 0; kk < 32; kk++) {
            float kv0, kv1, kv2, kv3;
            asm("ld.shared.v4.f32 {%0,%1,%2,%3}, [%4];"
                : "=f"(kv0), "=f"(kv1), "=f"(kv2), "=f"(kv3) : "r"(kaddr));
            unsigned long long kd0 = pack2(kv0, kv0);
            unsigned long long kd1 = pack2(kv1, kv1);
            unsigned long long kd2 = pack2(kv2, kv2);
            unsigned long long kd3 = pack2(kv3, kv3);
            #pragma unroll
            for (int pass = 0; pass < 3; pass++) {
                uint32_t ca = cbase + kk*1536 + pass*512;
                unsigned long long c01, c23, c45, c67;
                asm("ld.shared.v2.b64 {%0, %1}, [%2];" : "=l"(c01), "=l"(c23) : "r"(ca));
                asm("ld.shared.v2.b64 {%0, %1}, [%2];" : "=l"(c45), "=l"(c67) : "r"(ca + 16));
                unsigned long long* a = &accP[pass*16];
                a[ 0] = ffma2(kd0, c01, a[ 0]);
                a[ 1] = ffma2(kd0, c23, a[ 1]);
                a[ 2] = ffma2(kd0, c45, a[ 2]);
                a[ 3] = ffma2(kd0, c67, a[ 3]);
                a[ 4] = ffma2(kd1, c01, a[ 4]);
                a[ 5] = ffma2(kd1, c23, a[ 5]);
                a[ 6] = ffma2(kd1, c45, a[ 6]);
                a[ 7] = ffma2(kd1, c67, a[ 7]);
                a[ 8] = ffma2(kd2, c01, a[ 8]);
                a[ 9] = ffma2(kd2, c23, a[ 9]);
                a[10] = ffma2(kd2, c45, a[10]);
                a[11] = ffma2(kd2, c67, a[11]);
                a[12] = ffma2(kd3, c01, a[12]);
                a[13] = ffma2(kd3, c23, a[13]);
                a[14] = ffma2(kd3, c45, a[14]);
                a[15] = ffma2(kd3, c67, a[15]);
            }
            kaddr += 256;
        }
        __syncthreads();
        if (t + 2 < 12) issueC(t + 2);
        cpcommit();
    }

    // ---- epilogue: var_r += T[np r][m'] * K[m'][np r] ----
    float vacc[4] = {0.f, 0.f, 0.f, 0.f};
    #pragma unroll
    for (int pass = 0; pass < 3; pass++) {
        #pragma unroll
        for (int c = 0; c < 8; c++) {
            int mp = pass*128 + tx*8 + c;
            uint32_t ka = sK_u32 + (uint32_t)((mp*64 + r0) * 4);
            float k0, k1, k2, k3;
            asm("ld.shared.v4.f32 {%0,%1,%2,%3}, [%4];"
                : "=f"(k0), "=f"(k1), "=f"(k2), "=f"(k3) : "r"(ka));
            int cp = c >> 1;
            #pragma unroll
            for (int r = 0; r < 4; r++) {
                float lo, hi;
                unpack2(accP[pass*16 + r*4 + cp], lo, hi);
                float tval = (c & 1) ? hi : lo;
                float kr = (r == 0) ? k0 : (r == 1) ? k1 : (r == 2) ? k2 : k3;
                vacc[r] += tval * kr;
            }
        }
    }
    #pragma unroll
    for (int r = 0; r < 4; r++) {
        float s = vacc[r];
        s += __shfl_down_sync(0xffffffffu, s, 8, 16);
        s += __shfl_down_sync(0xffffffffu, s, 4, 16);
        s += __shfl_down_sync(0xffffffffu, s, 2, 16);
        s += __shfl_down_sync(0xffffffffu, s, 1, 16);
        if (tx == 0) svar[r0 + r] = s;
    }
    __syncthreads();
    if (tid < NIMG)
        out_var[(size_t)tid * PDIM + p] = v + svar[tid];
}

// ---------------- host launch ----------------
extern "C" void kernel_launch(void* const* d_in, const int* in_sizes, int n_in,
                              void* d_out, int out_size) {
    const float* X    = (const float*)d_in[0];
    const float* Z    = (const float*)d_in[1];
    const float* qmu  = (const float*)d_in[2];
    const float* qsq  = (const float*)d_in[3];
    const float* pvar = (const float*)d_in[4];
    const float* plen = (const float*)d_in[5];
    float* out = (float*)d_out;
    float* out_mean = out;
    float* out_var  = out + (size_t)NIMG*PDIM;

    float *pKuu, *pX1, *pW2, *pR, *pLs, *pE, *pT, *pCm;
    cudaGetSymbolAddress((void**)&pKuu, g_Kuu);
    cudaGetSymbolAddress((void**)&pX1,  g_X1);
    cudaGetSymbolAddress((void**)&pW2,  g_W2);
    cudaGetSymbolAddress((void**)&pR,   g_R);
    cudaGetSymbolAddress((void**)&pLs,  g_Ls);
    cudaGetSymbolAddress((void**)&pE,   g_E);
    cudaGetSymbolAddress((void**)&pT,   g_T);
    cudaGetSymbolAddress((void**)&pCm,  g_Cm);

    prep_kernel<<<64, 256>>>(X, Z, qsq, plen);
    zsq_kernel<<<2, 256>>>();
    kuu_kernel<<<(MDIM*MDIM + 255)/256, 256>>>(pvar);   // Kuu + X1

    // pair: R = 2I - Kuu*X1  ||  E = Ls*Ls^T - Kuu
    gemm_db<<<dim3(12,12,2), 256>>>(pKuu, pX1, pR, nullptr, 1, 0,
                                    pLs,  pLs, pE, pKuu,   2, 1);
    // W2 = X1 * R  (Newton iter 2)
    gemm_db<<<dim3(12,12,1), 256>>>(pX1, pR, pW2, nullptr, 0, 0,
                                    nullptr, nullptr, nullptr, nullptr, 0, 0);
    // T = W2 * E
    gemm_db<<<dim3(12,12,1), 256>>>(pW2, pE, pT, nullptr, 0, 0,
                                    nullptr, nullptr, nullptr, nullptr, 0, 0);
    // C = T * W2   (== W qS W - W up to Newton error)
    gemm_db<<<dim3(12,12,1), 256>>>(pT, pW2, pCm, nullptr, 0, 0,
                                    nullptr, nullptr, nullptr, nullptr, 0, 0);

    alpha_kernel<<<3, 128>>>(qmu);

    cudaFuncSetAttribute(mega_kernel, cudaFuncAttributeMaxDynamicSharedMemorySize, SMEM_MEGA_B);
    mega_kernel<<<PDIM, 256, SMEM_MEGA_B>>>(pvar, out_mean, out_var);
}